// round 1
// baseline (speedup 1.0000x reference)
#include <cuda_runtime.h>
#include <cstdint>

#define N_NODES 50000
#define N_EDGES 500000
#define TOT_SLOTS (N_EDGES + N_NODES)
#define HID 256

// ---------------- scratch (static __device__, no allocation) ----------------
__device__ float g_h1[(size_t)N_NODES * HID];   // 51.2 MB
__device__ float g_h2[(size_t)N_NODES * HID];   // 51.2 MB
__device__ float g_P [(size_t)N_NODES * HID];   // 51.2 MB
__device__ float g_Q [(size_t)N_NODES * HID];   // 51.2 MB
__device__ float g_as[N_NODES];
__device__ float g_ad[N_NODES];
__device__ int   g_deg[N_NODES];
__device__ int   g_off[N_NODES + 1];
__device__ int   g_cur[N_NODES];
__device__ int   g_srcidx[TOT_SLOTS];
__device__ int   g_is64;

// ---------------- edge index access (int32 vs int64 detected at runtime) ----
__global__ void detect_kernel(const unsigned int* __restrict__ w) {
    if (threadIdx.x == 0 && blockIdx.x == 0) {
        int all0 = 1;
        #pragma unroll
        for (int i = 0; i < 16; i++)
            if (w[2 * i + 1] != 0u) all0 = 0;
        g_is64 = all0;   // int64 little-endian: odd 32-bit words are zero (vals < 50000)
    }
}

__device__ __forceinline__ int edge_at(const void* ei, int which, int e) {
    if (g_is64) return (int)((const long long*)ei)[(size_t)which * N_EDGES + e];
    return ((const int*)ei)[(size_t)which * N_EDGES + e];
}

// ---------------- CSR build -------------------------------------------------
__global__ void init_deg_kernel() {
    int i = blockIdx.x * blockDim.x + threadIdx.x;
    if (i < N_NODES) g_deg[i] = 1;    // self loop pre-counted
}

__global__ void count_kernel(const void* __restrict__ ei) {
    int e = blockIdx.x * blockDim.x + threadIdx.x;
    if (e < N_EDGES) {
        int d = edge_at(ei, 1, e);
        atomicAdd(&g_deg[d], 1);
    }
}

// single-block exclusive scan of g_deg -> g_off; also places the self loop at
// slot g_off[i] and initializes the fill cursor to g_off[i]+1.
__global__ void scan_kernel() {
    __shared__ int sh[1024];
    __shared__ int s_carry;
    int tid = threadIdx.x;
    if (tid == 0) s_carry = 0;
    __syncthreads();
    for (int base = 0; base < N_NODES; base += 1024) {
        int carry = s_carry;
        int i = base + tid;
        int v = (i < N_NODES) ? g_deg[i] : 0;
        sh[tid] = v;
        __syncthreads();
        #pragma unroll
        for (int off = 1; off < 1024; off <<= 1) {
            int t = 0;
            if (tid >= off) t = sh[tid - off];
            __syncthreads();
            if (tid >= off) sh[tid] += t;
            __syncthreads();
        }
        int incl = sh[tid];
        int excl = carry + incl - v;
        if (i < N_NODES) {
            g_off[i] = excl;
            g_srcidx[excl] = i;     // self loop in slot 0 of segment
            g_cur[i] = excl + 1;
        }
        __syncthreads();
        if (tid == 0) s_carry = carry + sh[1023];
        __syncthreads();
    }
    if (threadIdx.x == 0) g_off[N_NODES] = s_carry;
}

__global__ void fill_kernel(const void* __restrict__ ei) {
    int e = blockIdx.x * blockDim.x + threadIdx.x;
    if (e < N_EDGES) {
        int s = edge_at(ei, 0, e);
        int d = edge_at(ei, 1, e);
        int pos = atomicAdd(&g_cur[d], 1);
        g_srcidx[pos] = s;
    }
}

// ---------------- SGEMM: C[M,N] = A[M,K] @ B[K,N] (+bias) -------------------
#define BM 64
#define BN 64
#define BK 16

__global__ __launch_bounds__(256) void sgemm_kernel(
    const float* __restrict__ A, const float* __restrict__ B,
    const float* __restrict__ bias, float* __restrict__ C,
    int M, int K, int N)
{
    __shared__ float As[BK][BM + 4];
    __shared__ float Bs[BK][BN + 4];
    int tid = threadIdx.x;
    int m0 = blockIdx.y * BM;
    int n0 = blockIdx.x * BN;
    int tx = tid & 15, ty = tid >> 4;
    int ty4 = ty * 4, tx4 = tx * 4;

    int aRow = tid >> 2, aCol = (tid & 3) * 4;   // A: 64 rows x 16 cols per tile
    int bRow = tid >> 4, bCol = (tid & 15) * 4;  // B: 16 rows x 64 cols per tile

    float acc[4][4];
    #pragma unroll
    for (int i = 0; i < 4; i++)
        #pragma unroll
        for (int j = 0; j < 4; j++) acc[i][j] = 0.f;

    for (int k0 = 0; k0 < K; k0 += BK) {
        float4 av = make_float4(0.f, 0.f, 0.f, 0.f);
        int gm = m0 + aRow;
        if (gm < M) av = *(const float4*)(A + (size_t)gm * K + k0 + aCol);
        As[aCol][aRow] = av.x; As[aCol + 1][aRow] = av.y;
        As[aCol + 2][aRow] = av.z; As[aCol + 3][aRow] = av.w;

        float4 bv = *(const float4*)(B + (size_t)(k0 + bRow) * N + n0 + bCol);
        *(float4*)&Bs[bRow][bCol] = bv;
        __syncthreads();

        #pragma unroll
        for (int kk = 0; kk < BK; kk++) {
            float a0 = As[kk][ty4], a1 = As[kk][ty4 + 1];
            float a2 = As[kk][ty4 + 2], a3 = As[kk][ty4 + 3];
            float4 b = *(const float4*)&Bs[kk][tx4];
            acc[0][0] += a0 * b.x; acc[0][1] += a0 * b.y; acc[0][2] += a0 * b.z; acc[0][3] += a0 * b.w;
            acc[1][0] += a1 * b.x; acc[1][1] += a1 * b.y; acc[1][2] += a1 * b.z; acc[1][3] += a1 * b.w;
            acc[2][0] += a2 * b.x; acc[2][1] += a2 * b.y; acc[2][2] += a2 * b.z; acc[2][3] += a2 * b.w;
            acc[3][0] += a3 * b.x; acc[3][1] += a3 * b.y; acc[3][2] += a3 * b.z; acc[3][3] += a3 * b.w;
        }
        __syncthreads();
    }

    float4 bb = make_float4(0.f, 0.f, 0.f, 0.f);
    if (bias) bb = *(const float4*)(bias + n0 + tx4);
    #pragma unroll
    for (int i = 0; i < 4; i++) {
        int gm = m0 + ty4 + i;
        if (gm < M) {
            float4 v = make_float4(acc[i][0] + bb.x, acc[i][1] + bb.y,
                                   acc[i][2] + bb.z, acc[i][3] + bb.w);
            *(float4*)(C + (size_t)gm * N + n0 + tx4) = v;
        }
    }
}

// ---------------- per-node attention coefficients ---------------------------
__global__ __launch_bounds__(256) void alpha_kernel(
    const float* __restrict__ h,
    const float* __restrict__ asrc, const float* __restrict__ adst)
{
    int gw = (blockIdx.x * blockDim.x + threadIdx.x) >> 5;
    int lane = threadIdx.x & 31;
    if (gw >= N_NODES) return;
    const float4* h4 = (const float4*)(h + (size_t)gw * HID);
    const float4* s4 = (const float4*)asrc;
    const float4* d4 = (const float4*)adst;
    float4 v0 = h4[lane], v1 = h4[lane + 32];
    float4 a0 = s4[lane], a1 = s4[lane + 32];
    float4 b0 = d4[lane], b1 = d4[lane + 32];
    float ps = v0.x * a0.x + v0.y * a0.y + v0.z * a0.z + v0.w * a0.w
             + v1.x * a1.x + v1.y * a1.y + v1.z * a1.z + v1.w * a1.w;
    float pd = v0.x * b0.x + v0.y * b0.y + v0.z * b0.z + v0.w * b0.w
             + v1.x * b1.x + v1.y * b1.y + v1.z * b1.z + v1.w * b1.w;
    #pragma unroll
    for (int o = 16; o > 0; o >>= 1) {
        ps += __shfl_down_sync(0xFFFFFFFFu, ps, o);
        pd += __shfl_down_sync(0xFFFFFFFFu, pd, o);
    }
    if (lane == 0) { g_as[gw] = ps; g_ad[gw] = pd; }
}

// ---------------- softmax-weighted aggregation (warp per dst node) ----------
__global__ __launch_bounds__(256) void aggregate_kernel(
    const float* __restrict__ h, const float* __restrict__ bias,
    int do_relu, float* __restrict__ out)
{
    int n = (blockIdx.x * blockDim.x + threadIdx.x) >> 5;
    int lane = threadIdx.x & 31;
    if (n >= N_NODES) return;
    int start = g_off[n], end = g_off[n + 1];
    float ad = g_ad[n];
    float m = -3.4e38f, l = 0.f;
    float4 acc0 = make_float4(0.f, 0.f, 0.f, 0.f);
    float4 acc1 = make_float4(0.f, 0.f, 0.f, 0.f);

    for (int j = start; j < end; j++) {
        int s = g_srcidx[j];
        float e = g_as[s] + ad;
        e = e > 0.f ? e : 0.2f * e;           // LeakyReLU(0.2)
        if (e > m) {
            float sc = __expf(m - e);          // first iter: exp(-huge) = 0
            l *= sc;
            acc0.x *= sc; acc0.y *= sc; acc0.z *= sc; acc0.w *= sc;
            acc1.x *= sc; acc1.y *= sc; acc1.z *= sc; acc1.w *= sc;
            m = e;
        }
        float w = __expf(e - m);
        l += w;
        const float4* hr = (const float4*)(h + (size_t)s * HID);
        float4 v0 = hr[lane], v1 = hr[lane + 32];
        acc0.x += w * v0.x; acc0.y += w * v0.y; acc0.z += w * v0.z; acc0.w += w * v0.w;
        acc1.x += w * v1.x; acc1.y += w * v1.y; acc1.z += w * v1.z; acc1.w += w * v1.w;
    }
    float inv = 1.f / l;
    const float4* b4 = (const float4*)bias;
    float4 b0 = b4[lane], b1 = b4[lane + 32];
    float4 r0 = make_float4(acc0.x * inv + b0.x, acc0.y * inv + b0.y,
                            acc0.z * inv + b0.z, acc0.w * inv + b0.w);
    float4 r1 = make_float4(acc1.x * inv + b1.x, acc1.y * inv + b1.y,
                            acc1.z * inv + b1.z, acc1.w * inv + b1.w);
    if (do_relu) {
        r0.x = fmaxf(r0.x, 0.f); r0.y = fmaxf(r0.y, 0.f);
        r0.z = fmaxf(r0.z, 0.f); r0.w = fmaxf(r0.w, 0.f);
        r1.x = fmaxf(r1.x, 0.f); r1.y = fmaxf(r1.y, 0.f);
        r1.z = fmaxf(r1.z, 0.f); r1.w = fmaxf(r1.w, 0.f);
    }
    float4* o4 = (float4*)(out + (size_t)n * HID);
    o4[lane] = r0;
    o4[lane + 32] = r1;
}

// ---------------- edge output: out[e] = P[src[e]] + Q[dst[e]] ---------------
__global__ __launch_bounds__(256) void edge_out_kernel(
    const void* __restrict__ ei,
    const float* __restrict__ P, const float* __restrict__ Q,
    float* __restrict__ out)
{
    int gw = (blockIdx.x * blockDim.x + threadIdx.x) >> 5;
    int lane = threadIdx.x & 31;
    if (gw >= N_EDGES) return;
    int s = edge_at(ei, 0, gw);
    int d = edge_at(ei, 1, gw);
    const float4* P4 = (const float4*)(P + (size_t)s * HID);
    const float4* Q4 = (const float4*)(Q + (size_t)d * HID);
    float4* o4 = (float4*)(out + (size_t)gw * HID);
    float4 p0 = P4[lane], q0 = Q4[lane];
    float4 p1 = P4[lane + 32], q1 = Q4[lane + 32];
    o4[lane]      = make_float4(p0.x + q0.x, p0.y + q0.y, p0.z + q0.z, p0.w + q0.w);
    o4[lane + 32] = make_float4(p1.x + q1.x, p1.y + q1.y, p1.z + q1.z, p1.w + q1.w);
}

// ---------------- host launch ----------------------------------------------
extern "C" void kernel_launch(void* const* d_in, const int* in_sizes, int n_in,
                              void* d_out, int out_size)
{
    const float* x      = (const float*)d_in[0];
    const void*  ei     = d_in[1];
    const float* W1     = (const float*)d_in[2];
    const float* a1_src = (const float*)d_in[3];
    const float* a1_dst = (const float*)d_in[4];
    const float* b1     = (const float*)d_in[5];
    const float* W2     = (const float*)d_in[6];
    const float* a2_src = (const float*)d_in[7];
    const float* a2_dst = (const float*)d_in[8];
    const float* b2     = (const float*)d_in[9];
    const float* lin_W  = (const float*)d_in[10];
    const float* lin_b  = (const float*)d_in[11];
    float* out = (float*)d_out;

    float *h1, *h2, *P, *Q;
    cudaGetSymbolAddress((void**)&h1, g_h1);
    cudaGetSymbolAddress((void**)&h2, g_h2);
    cudaGetSymbolAddress((void**)&P,  g_P);
    cudaGetSymbolAddress((void**)&Q,  g_Q);

    const int TB = 256;
    int ebk = (N_EDGES + TB - 1) / TB;           // 1954
    int nbk = (N_NODES + TB - 1) / TB;           // 196
    int wbk_n = (N_NODES * 32 + TB - 1) / TB;    // 6250 (warp per node)
    int wbk_e = (N_EDGES * 32 + TB - 1) / TB;    // 62500 (warp per edge)

    // dtype detect + CSR build (graph identical both layers)
    detect_kernel<<<1, 32>>>((const unsigned int*)ei);
    init_deg_kernel<<<nbk, TB>>>();
    count_kernel<<<ebk, TB>>>(ei);
    scan_kernel<<<1, 1024>>>();
    fill_kernel<<<ebk, TB>>>(ei);

    dim3 gemm_grid(HID / BN, (N_NODES + BM - 1) / BM);  // (4, 782)

    // layer 1: h1 = x @ W1 ; softmax-aggregate (+b1, relu) -> h2
    sgemm_kernel<<<gemm_grid, TB>>>(x, W1, nullptr, h1, N_NODES, 128, HID);
    alpha_kernel<<<wbk_n, TB>>>(h1, a1_src, a1_dst);
    aggregate_kernel<<<wbk_n, TB>>>(h1, b1, 1, h2);

    // layer 2: h1 = h2 @ W2 ; aggregate (+b2) -> h2
    sgemm_kernel<<<gemm_grid, TB>>>(h2, W2, nullptr, h1, N_NODES, HID, HID);
    alpha_kernel<<<wbk_n, TB>>>(h1, a2_src, a2_dst);
    aggregate_kernel<<<wbk_n, TB>>>(h1, b2, 0, h2);

    // final: P = h2 @ lin_W[:256] + lin_b ; Q = h2 @ lin_W[256:]
    sgemm_kernel<<<gemm_grid, TB>>>(h2, lin_W, lin_b, P, N_NODES, HID, HID);
    sgemm_kernel<<<gemm_grid, TB>>>(h2, lin_W + (size_t)HID * HID, nullptr, Q,
                                    N_NODES, HID, HID);

    // out[e] = P[src] + Q[dst]
    edge_out_kernel<<<wbk_e, TB>>>(ei, P, Q, out);
}

// round 4
// speedup vs baseline: 1.4220x; 1.4220x over previous
#include <cuda_runtime.h>
#include <cuda_bf16.h>
#include <cstdint>

#define N_NODES 50000
#define N_EDGES 500000
#define TOT_SLOTS (N_EDGES + N_NODES)
#define HID 256

// ---------------- scratch (static __device__, no allocation) ----------------
__device__ float g_h1[(size_t)N_NODES * HID];   // 51.2 MB
__device__ float g_h2[(size_t)N_NODES * HID];   // 51.2 MB
__device__ float g_P [(size_t)N_NODES * HID];   // 51.2 MB
__device__ float g_Q [(size_t)N_NODES * HID];   // 51.2 MB
__device__ float g_as[N_NODES];
__device__ float g_ad[N_NODES];
__device__ int   g_deg[N_NODES];
__device__ int   g_off[N_NODES + 1];
__device__ int   g_cur[N_NODES];
__device__ int   g_srcidx[TOT_SLOTS];
__device__ int   g_is64;

// ---------------- edge index access (int32 vs int64 detected at runtime) ----
__global__ void detect_kernel(const unsigned int* __restrict__ w) {
    if (threadIdx.x == 0 && blockIdx.x == 0) {
        int all0 = 1;
        #pragma unroll
        for (int i = 0; i < 16; i++)
            if (w[2 * i + 1] != 0u) all0 = 0;
        g_is64 = all0;   // int64 little-endian: odd 32-bit words zero (vals < 50000)
    }
}

__device__ __forceinline__ int edge_at(const void* ei, int which, int e) {
    if (g_is64) return (int)((const long long*)ei)[(size_t)which * N_EDGES + e];
    return ((const int*)ei)[(size_t)which * N_EDGES + e];
}

// ---------------- CSR build -------------------------------------------------
__global__ void init_deg_kernel() {
    int i = blockIdx.x * blockDim.x + threadIdx.x;
    if (i < N_NODES) g_deg[i] = 1;    // self loop pre-counted
}

__global__ void count_kernel(const void* __restrict__ ei) {
    int e = blockIdx.x * blockDim.x + threadIdx.x;
    if (e < N_EDGES) {
        int d = edge_at(ei, 1, e);
        atomicAdd(&g_deg[d], 1);
    }
}

// Fast single-block scan: 1024 threads x 49 serial elems + shfl block scan.
__global__ void scan_kernel() {
    const int CH = 49;                 // 1024*49 = 50176 >= N_NODES
    __shared__ int wsum[32];
    __shared__ int s_total;
    int t = threadIdx.x;
    int lane = t & 31, w = t >> 5;
    int base = t * CH;

    int sum = 0;
    for (int i = 0; i < CH; i++) {
        int idx = base + i;
        if (idx < N_NODES) sum += g_deg[idx];
    }
    // warp inclusive scan of per-thread sums
    int v = sum;
    #pragma unroll
    for (int o = 1; o < 32; o <<= 1) {
        int u = __shfl_up_sync(0xFFFFFFFFu, v, o);
        if (lane >= o) v += u;
    }
    if (lane == 31) wsum[w] = v;
    __syncthreads();
    if (w == 0) {
        int x = wsum[lane];
        #pragma unroll
        for (int o = 1; o < 32; o <<= 1) {
            int u = __shfl_up_sync(0xFFFFFFFFu, x, o);
            if (lane >= o) x += u;
        }
        wsum[lane] = x;
        if (lane == 31) s_total = x;
    }
    __syncthreads();
    int prefix = v - sum + (w > 0 ? wsum[w - 1] : 0);   // exclusive prefix
    int run = prefix;
    for (int i = 0; i < CH; i++) {
        int idx = base + i;
        if (idx < N_NODES) {
            int d = g_deg[idx];
            g_off[idx] = run;
            g_srcidx[run] = idx;       // self loop in slot 0 of segment
            g_cur[idx] = run + 1;
            run += d;
        }
    }
    if (t == 0) g_off[N_NODES] = s_total;
}

__global__ void fill_kernel(const void* __restrict__ ei) {
    int e = blockIdx.x * blockDim.x + threadIdx.x;
    if (e < N_EDGES) {
        int s = edge_at(ei, 0, e);
        int d = edge_at(ei, 1, e);
        int pos = atomicAdd(&g_cur[d], 1);
        g_srcidx[pos] = s;
    }
}

// ---------------- bf16x3 tensor-core GEMM -----------------------------------
// C[M,N] = A[M,K] @ B[K,N] (+bias). fp32 in/out; each operand split hi+lo bf16,
// products ah*bh + ah*bl + al*bh accumulated in fp32 (error ~1e-5 rel).
// Block: 256 threads (8 warps, 4Mx2N), block tile 128x64x32, warp tile 32x32.

__device__ __forceinline__ void bf16_split2(float x, float y,
                                            uint32_t& hi, uint32_t& lo) {
    __nv_bfloat16 xh = __float2bfloat16_rn(x);
    __nv_bfloat16 yh = __float2bfloat16_rn(y);
    float xr = x - __bfloat162float(xh);
    float yr = y - __bfloat162float(yh);
    __nv_bfloat162 h = __halves2bfloat162(xh, yh);
    __nv_bfloat162 l = __halves2bfloat162(__float2bfloat16_rn(xr),
                                          __float2bfloat16_rn(yr));
    hi = *reinterpret_cast<uint32_t*>(&h);
    lo = *reinterpret_cast<uint32_t*>(&l);
}

__device__ __forceinline__ void mma_bf16(float* c, const uint32_t* a,
                                         const uint32_t* b) {
    asm volatile(
        "mma.sync.aligned.m16n8k16.row.col.f32.bf16.bf16.f32 "
        "{%0,%1,%2,%3}, {%4,%5,%6,%7}, {%8,%9}, {%0,%1,%2,%3};\n"
        : "+f"(c[0]), "+f"(c[1]), "+f"(c[2]), "+f"(c[3])
        : "r"(a[0]), "r"(a[1]), "r"(a[2]), "r"(a[3]), "r"(b[0]), "r"(b[1]));
}

__global__ __launch_bounds__(256) void mma_gemm_kernel(
    const float* __restrict__ A, const float* __restrict__ B,
    const float* __restrict__ bias, float* __restrict__ C,
    int M, int K, int N)
{
    // k-pair-packed bf16x2 words; row stride 17 words (16 pairs + pad)
    __shared__ uint32_t As_hi[128][17], As_lo[128][17];
    __shared__ uint32_t Bs_hi[64][17],  Bs_lo[64][17];

    int tid = threadIdx.x;
    int lane = tid & 31;
    int warp = tid >> 5;
    int warpM = warp >> 1;        // 0..3 -> 32 rows each
    int warpN = warp & 1;         // 0..1 -> 32 cols each
    int g = lane >> 2, tg = lane & 3;

    int m0 = blockIdx.y * 128;
    int n0 = blockIdx.x * 64;

    float acc[2][4][4];
    #pragma unroll
    for (int mt = 0; mt < 2; mt++)
        #pragma unroll
        for (int nt = 0; nt < 4; nt++)
            #pragma unroll
            for (int i = 0; i < 4; i++) acc[mt][nt][i] = 0.f;

    for (int k0 = 0; k0 < K; k0 += 32) {
        // load + split A tile: 128 rows x 32 cols = 1024 float4, 4/thread
        #pragma unroll
        for (int i = 0; i < 4; i++) {
            int f = tid + i * 256;
            int r = f >> 3;
            int q = f & 7;
            float4 v = make_float4(0.f, 0.f, 0.f, 0.f);
            int gm = m0 + r;
            if (gm < M) v = *(const float4*)(A + (size_t)gm * K + k0 + q * 4);
            uint32_t h0, l0, h1, l1;
            bf16_split2(v.x, v.y, h0, l0);
            bf16_split2(v.z, v.w, h1, l1);
            As_hi[r][q * 2] = h0;     As_lo[r][q * 2] = l0;
            As_hi[r][q * 2 + 1] = h1; As_lo[r][q * 2 + 1] = l1;
        }
        // load + split B tile: 32 rows x 64 cols, transposed to n-major k-pairs
        {
            int kp = tid >> 4;        // 0..15 (k pair index)
            int n4 = tid & 15;        // 0..15 (group of 4 n)
            const float* bp = B + (size_t)(k0 + kp * 2) * N + n0 + n4 * 4;
            float4 r0 = *(const float4*)bp;
            float4 r1 = *(const float4*)(bp + N);
            uint32_t h, l;
            bf16_split2(r0.x, r1.x, h, l); Bs_hi[n4*4+0][kp] = h; Bs_lo[n4*4+0][kp] = l;
            bf16_split2(r0.y, r1.y, h, l); Bs_hi[n4*4+1][kp] = h; Bs_lo[n4*4+1][kp] = l;
            bf16_split2(r0.z, r1.z, h, l); Bs_hi[n4*4+2][kp] = h; Bs_lo[n4*4+2][kp] = l;
            bf16_split2(r0.w, r1.w, h, l); Bs_hi[n4*4+3][kp] = h; Bs_lo[n4*4+3][kp] = l;
        }
        __syncthreads();

        #pragma unroll
        for (int ks = 0; ks < 2; ks++) {
            uint32_t ah[2][4], al[2][4], bh[4][2], bl[4][2];
            int kp = ks * 8 + tg;
            #pragma unroll
            for (int mt = 0; mt < 2; mt++) {
                int mr = warpM * 32 + mt * 16 + g;
                ah[mt][0] = As_hi[mr][kp];       al[mt][0] = As_lo[mr][kp];
                ah[mt][1] = As_hi[mr + 8][kp];   al[mt][1] = As_lo[mr + 8][kp];
                ah[mt][2] = As_hi[mr][kp + 4];   al[mt][2] = As_lo[mr][kp + 4];
                ah[mt][3] = As_hi[mr + 8][kp+4]; al[mt][3] = As_lo[mr + 8][kp+4];
            }
            #pragma unroll
            for (int nt = 0; nt < 4; nt++) {
                int nc = warpN * 32 + nt * 8 + g;
                bh[nt][0] = Bs_hi[nc][kp];       bl[nt][0] = Bs_lo[nc][kp];
                bh[nt][1] = Bs_hi[nc][kp + 4];   bl[nt][1] = Bs_lo[nc][kp + 4];
            }
            #pragma unroll
            for (int mt = 0; mt < 2; mt++)
                #pragma unroll
                for (int nt = 0; nt < 4; nt++) {
                    mma_bf16(acc[mt][nt], ah[mt], bh[nt]);
                    mma_bf16(acc[mt][nt], ah[mt], bl[nt]);
                    mma_bf16(acc[mt][nt], al[mt], bh[nt]);
                }
        }
        __syncthreads();
    }

    // epilogue
    #pragma unroll
    for (int nt = 0; nt < 4; nt++) {
        int col = n0 + warpN * 32 + nt * 8 + tg * 2;
        float2 bb = make_float2(0.f, 0.f);
        if (bias) { bb.x = bias[col]; bb.y = bias[col + 1]; }
        #pragma unroll
        for (int mt = 0; mt < 2; mt++) {
            int r0 = m0 + warpM * 32 + mt * 16 + g;
            if (r0 < M) {
                float2 v = make_float2(acc[mt][nt][0] + bb.x, acc[mt][nt][1] + bb.y);
                *(float2*)(C + (size_t)r0 * N + col) = v;
            }
            if (r0 + 8 < M) {
                float2 v = make_float2(acc[mt][nt][2] + bb.x, acc[mt][nt][3] + bb.y);
                *(float2*)(C + (size_t)(r0 + 8) * N + col) = v;
            }
        }
    }
}

// ---------------- per-node attention coefficients ---------------------------
__global__ __launch_bounds__(256) void alpha_kernel(
    const float* __restrict__ h,
    const float* __restrict__ asrc, const float* __restrict__ adst)
{
    int gw = (blockIdx.x * blockDim.x + threadIdx.x) >> 5;
    int lane = threadIdx.x & 31;
    if (gw >= N_NODES) return;
    const float4* h4 = (const float4*)(h + (size_t)gw * HID);
    const float4* s4 = (const float4*)asrc;
    const float4* d4 = (const float4*)adst;
    float4 v0 = h4[lane], v1 = h4[lane + 32];
    float4 a0 = s4[lane], a1 = s4[lane + 32];
    float4 b0 = d4[lane], b1 = d4[lane + 32];
    float ps = v0.x * a0.x + v0.y * a0.y + v0.z * a0.z + v0.w * a0.w
             + v1.x * a1.x + v1.y * a1.y + v1.z * a1.z + v1.w * a1.w;
    float pd = v0.x * b0.x + v0.y * b0.y + v0.z * b0.z + v0.w * b0.w
             + v1.x * b1.x + v1.y * b1.y + v1.z * b1.z + v1.w * b1.w;
    #pragma unroll
    for (int o = 16; o > 0; o >>= 1) {
        ps += __shfl_down_sync(0xFFFFFFFFu, ps, o);
        pd += __shfl_down_sync(0xFFFFFFFFu, pd, o);
    }
    if (lane == 0) { g_as[gw] = ps; g_ad[gw] = pd; }
}

// ---------------- softmax-weighted aggregation (warp per dst node) ----------
__global__ __launch_bounds__(256) void aggregate_kernel(
    const float* __restrict__ h, const float* __restrict__ bias,
    int do_relu, float* __restrict__ out)
{
    int n = (blockIdx.x * blockDim.x + threadIdx.x) >> 5;
    int lane = threadIdx.x & 31;
    if (n >= N_NODES) return;
    int start = g_off[n], end = g_off[n + 1];
    float ad = g_ad[n];
    float m = -3.4e38f, l = 0.f;
    float4 acc0 = make_float4(0.f, 0.f, 0.f, 0.f);
    float4 acc1 = make_float4(0.f, 0.f, 0.f, 0.f);

    for (int j = start; j < end; j++) {
        int s = g_srcidx[j];
        float e = g_as[s] + ad;
        e = e > 0.f ? e : 0.2f * e;           // LeakyReLU(0.2)
        if (e > m) {
            float sc = __expf(m - e);          // first iter: exp(-huge) = 0
            l *= sc;
            acc0.x *= sc; acc0.y *= sc; acc0.z *= sc; acc0.w *= sc;
            acc1.x *= sc; acc1.y *= sc; acc1.z *= sc; acc1.w *= sc;
            m = e;
        }
        float w = __expf(e - m);
        l += w;
        const float4* hr = (const float4*)(h + (size_t)s * HID);
        float4 v0 = hr[lane], v1 = hr[lane + 32];
        acc0.x += w * v0.x; acc0.y += w * v0.y; acc0.z += w * v0.z; acc0.w += w * v0.w;
        acc1.x += w * v1.x; acc1.y += w * v1.y; acc1.z += w * v1.z; acc1.w += w * v1.w;
    }
    float inv = 1.f / l;
    const float4* b4 = (const float4*)bias;
    float4 b0 = b4[lane], b1 = b4[lane + 32];
    float4 r0 = make_float4(acc0.x * inv + b0.x, acc0.y * inv + b0.y,
                            acc0.z * inv + b0.z, acc0.w * inv + b0.w);
    float4 r1 = make_float4(acc1.x * inv + b1.x, acc1.y * inv + b1.y,
                            acc1.z * inv + b1.z, acc1.w * inv + b1.w);
    if (do_relu) {
        r0.x = fmaxf(r0.x, 0.f); r0.y = fmaxf(r0.y, 0.f);
        r0.z = fmaxf(r0.z, 0.f); r0.w = fmaxf(r0.w, 0.f);
        r1.x = fmaxf(r1.x, 0.f); r1.y = fmaxf(r1.y, 0.f);
        r1.z = fmaxf(r1.z, 0.f); r1.w = fmaxf(r1.w, 0.f);
    }
    float4* o4 = (float4*)(out + (size_t)n * HID);
    o4[lane] = r0;
    o4[lane + 32] = r1;
}

// ---------------- edge output: out[e] = P[src[e]] + Q[dst[e]] ---------------
__global__ __launch_bounds__(256) void edge_out_kernel(
    const void* __restrict__ ei,
    const float* __restrict__ P, const float* __restrict__ Q,
    float* __restrict__ out)
{
    int gw = (blockIdx.x * blockDim.x + threadIdx.x) >> 5;
    int lane = threadIdx.x & 31;
    if (gw >= N_EDGES) return;
    int s = edge_at(ei, 0, gw);
    int d = edge_at(ei, 1, gw);
    const float4* P4 = (const float4*)(P + (size_t)s * HID);
    const float4* Q4 = (const float4*)(Q + (size_t)d * HID);
    float4* o4 = (float4*)(out + (size_t)gw * HID);
    float4 p0 = P4[lane], q0 = Q4[lane];
    float4 p1 = P4[lane + 32], q1 = Q4[lane + 32];
    o4[lane]      = make_float4(p0.x + q0.x, p0.y + q0.y, p0.z + q0.z, p0.w + q0.w);
    o4[lane + 32] = make_float4(p1.x + q1.x, p1.y + q1.y, p1.z + q1.z, p1.w + q1.w);
}

// ---------------- host launch ----------------------------------------------
extern "C" void kernel_launch(void* const* d_in, const int* in_sizes, int n_in,
                              void* d_out, int out_size)
{
    const float* x      = (const float*)d_in[0];
    const void*  ei     = d_in[1];
    const float* W1     = (const float*)d_in[2];
    const float* a1_src = (const float*)d_in[3];
    const float* a1_dst = (const float*)d_in[4];
    const float* b1     = (const float*)d_in[5];
    const float* W2     = (const float*)d_in[6];
    const float* a2_src = (const float*)d_in[7];
    const float* a2_dst = (const float*)d_in[8];
    const float* b2     = (const float*)d_in[9];
    const float* lin_W  = (const float*)d_in[10];
    const float* lin_b  = (const float*)d_in[11];
    float* out = (float*)d_out;

    float *h1, *h2, *P, *Q;
    cudaGetSymbolAddress((void**)&h1, g_h1);
    cudaGetSymbolAddress((void**)&h2, g_h2);
    cudaGetSymbolAddress((void**)&P,  g_P);
    cudaGetSymbolAddress((void**)&Q,  g_Q);

    const int TB = 256;
    int ebk = (N_EDGES + TB - 1) / TB;
    int nbk = (N_NODES + TB - 1) / TB;
    int wbk_n = (N_NODES * 32 + TB - 1) / TB;    // warp per node
    int wbk_e = (N_EDGES * 32 + TB - 1) / TB;    // warp per edge

    // dtype detect + CSR build (graph identical both layers)
    detect_kernel<<<1, 32>>>((const unsigned int*)ei);
    init_deg_kernel<<<nbk, TB>>>();
    count_kernel<<<ebk, TB>>>(ei);
    scan_kernel<<<1, 1024>>>();
    fill_kernel<<<ebk, TB>>>(ei);

    dim3 gemm_grid(HID / 64, (N_NODES + 127) / 128);  // (4, 391)

    // layer 1: h1 = x @ W1 ; softmax-aggregate (+b1, relu) -> h2
    mma_gemm_kernel<<<gemm_grid, TB>>>(x, W1, nullptr, h1, N_NODES, 128, HID);
    alpha_kernel<<<wbk_n, TB>>>(h1, a1_src, a1_dst);
    aggregate_kernel<<<wbk_n, TB>>>(h1, b1, 1, h2);

    // layer 2: h1 = h2 @ W2 ; aggregate (+b2) -> h2
    mma_gemm_kernel<<<gemm_grid, TB>>>(h2, W2, nullptr, h1, N_NODES, HID, HID);
    alpha_kernel<<<wbk_n, TB>>>(h1, a2_src, a2_dst);
    aggregate_kernel<<<wbk_n, TB>>>(h1, b2, 0, h2);

    // final: P = h2 @ lin_W[:256] + lin_b ; Q = h2 @ lin_W[256:]
    mma_gemm_kernel<<<gemm_grid, TB>>>(h2, lin_W, lin_b, P, N_NODES, HID, HID);
    mma_gemm_kernel<<<gemm_grid, TB>>>(h2, lin_W + (size_t)HID * HID, nullptr, Q,
                                       N_NODES, HID, HID);

    // out[e] = P[src] + Q[dst]
    edge_out_kernel<<<wbk_e, TB>>>(ei, P, Q, out);
}

// round 7
// speedup vs baseline: 1.6492x; 1.1597x over previous
#include <cuda_runtime.h>
#include <cuda_bf16.h>
#include <cstdint>

#define N_NODES 50000
#define N_EDGES 500000
#define TOT_SLOTS (N_EDGES + N_NODES)
#define HID 256
#define SCAN_B 512
#define SCAN_NB ((N_NODES + SCAN_B - 1) / SCAN_B)   // 98

// ---------------- scratch (static __device__, no allocation) ----------------
__device__ float g_h1[(size_t)N_NODES * HID];   // 51.2 MB
__device__ float g_h2[(size_t)N_NODES * HID];   // 51.2 MB
__device__ float g_P [(size_t)N_NODES * HID];   // 51.2 MB
__device__ float g_Q [(size_t)N_NODES * HID];   // 51.2 MB
__device__ float g_as[N_NODES];
__device__ float g_ad[N_NODES];
__device__ int   g_deg[N_NODES];
__device__ int   g_off[N_NODES + 1];
__device__ int   g_cur[N_NODES];
__device__ int   g_srcidx[TOT_SLOTS];
__device__ int   g_bsum[SCAN_NB];
__device__ int   g_boff[SCAN_NB];
__device__ int   g_is64;

// ---------------- edge index access (int32 vs int64 detected at runtime) ----
__global__ void detect_kernel(const unsigned int* __restrict__ w) {
    if (threadIdx.x == 0 && blockIdx.x == 0) {
        int all0 = 1;
        #pragma unroll
        for (int i = 0; i < 16; i++)
            if (w[2 * i + 1] != 0u) all0 = 0;
        g_is64 = all0;   // int64 little-endian: odd 32-bit words zero (vals < 50000)
    }
}

__device__ __forceinline__ int edge_at(const void* ei, int which, int e) {
    if (g_is64) return (int)((const long long*)ei)[(size_t)which * N_EDGES + e];
    return ((const int*)ei)[(size_t)which * N_EDGES + e];
}

// ---------------- CSR build -------------------------------------------------
__global__ void init_deg_kernel() {
    int i = blockIdx.x * blockDim.x + threadIdx.x;
    if (i < N_NODES) g_deg[i] = 1;    // self loop pre-counted
}

__global__ void count_kernel(const void* __restrict__ ei) {
    int e = blockIdx.x * blockDim.x + threadIdx.x;
    if (e < N_EDGES) {
        int d = edge_at(ei, 1, e);
        atomicAdd(&g_deg[d], 1);
    }
}

// Phase 1: per-block (512 nodes) degree sums. Fully coalesced, 98 blocks.
__global__ __launch_bounds__(SCAN_B) void blocksum_kernel() {
    __shared__ int ws[SCAN_B / 32];
    int tid = threadIdx.x;
    int lane = tid & 31, w = tid >> 5;
    int i = blockIdx.x * SCAN_B + tid;
    int v = (i < N_NODES) ? g_deg[i] : 0;
    #pragma unroll
    for (int o = 16; o > 0; o >>= 1) v += __shfl_down_sync(0xFFFFFFFFu, v, o);
    if (lane == 0) ws[w] = v;
    __syncthreads();
    if (w == 0) {
        int x = (lane < SCAN_B / 32) ? ws[lane] : 0;
        #pragma unroll
        for (int o = 8; o > 0; o >>= 1) x += __shfl_down_sync(0xFFFFFFFFu, x, o);
        if (lane == 0) g_bsum[blockIdx.x] = x;
    }
}

// Phase 2: one warp exclusive-scans the 98 block sums.
__global__ void scan_blocks_kernel() {
    int lane = threadIdx.x;          // 32 threads
    int base = lane * 4;             // 4 chunks/lane covers 128 >= 98
    int vals[4];
    int sum = 0;
    #pragma unroll
    for (int k = 0; k < 4; k++) {
        int idx = base + k;
        vals[k] = (idx < SCAN_NB) ? g_bsum[idx] : 0;
        sum += vals[k];
    }
    int v = sum;
    #pragma unroll
    for (int o = 1; o < 32; o <<= 1) {
        int u = __shfl_up_sync(0xFFFFFFFFu, v, o);
        if (lane >= o) v += u;
    }
    int run = v - sum;               // exclusive prefix
    #pragma unroll
    for (int k = 0; k < 4; k++) {
        int idx = base + k;
        if (idx < SCAN_NB) { g_boff[idx] = run; run += vals[k]; }
    }
    if (lane == 31) g_off[N_NODES] = v;   // grand total
}

// Phase 3: block-level scan + write offsets / cursors / self-loop slots.
__global__ __launch_bounds__(SCAN_B) void write_off_kernel() {
    __shared__ int ws[SCAN_B / 32];
    int tid = threadIdx.x;
    int lane = tid & 31, w = tid >> 5;
    int i = blockIdx.x * SCAN_B + tid;
    int d = (i < N_NODES) ? g_deg[i] : 0;
    int v = d;
    #pragma unroll
    for (int o = 1; o < 32; o <<= 1) {
        int u = __shfl_up_sync(0xFFFFFFFFu, v, o);
        if (lane >= o) v += u;
    }
    if (lane == 31) ws[w] = v;
    __syncthreads();
    if (w == 0) {
        int x = (lane < SCAN_B / 32) ? ws[lane] : 0;
        #pragma unroll
        for (int o = 1; o < 32; o <<= 1) {
            int u = __shfl_up_sync(0xFFFFFFFFu, x, o);
            if (lane >= o) x += u;
        }
        if (lane < SCAN_B / 32) ws[lane] = x;
    }
    __syncthreads();
    int excl = v - d + (w > 0 ? ws[w - 1] : 0) + g_boff[blockIdx.x];
    if (i < N_NODES) {
        g_off[i] = excl;
        g_srcidx[excl] = i;          // self loop in slot 0 of segment
        g_cur[i] = excl + 1;
    }
}

__global__ void fill_kernel(const void* __restrict__ ei) {
    int e = blockIdx.x * blockDim.x + threadIdx.x;
    if (e < N_EDGES) {
        int s = edge_at(ei, 0, e);
        int d = edge_at(ei, 1, e);
        int pos = atomicAdd(&g_cur[d], 1);
        g_srcidx[pos] = s;
    }
}

// ---------------- bf16x3 tensor-core GEMM -----------------------------------
// C[M,N] = A[M,K] @ B[K,N] (+bias). fp32 in/out; each operand split hi+lo bf16,
// products ah*bh + ah*bl + al*bh accumulated in fp32 (error ~1e-5 rel).
// Block: 256 threads (8 warps, 4Mx2N), block tile 128x64x32, warp tile 32x32.

__device__ __forceinline__ void bf16_split2(float x, float y,
                                            uint32_t& hi, uint32_t& lo) {
    __nv_bfloat16 xh = __float2bfloat16_rn(x);
    __nv_bfloat16 yh = __float2bfloat16_rn(y);
    float xr = x - __bfloat162float(xh);
    float yr = y - __bfloat162float(yh);
    __nv_bfloat162 h = __halves2bfloat162(xh, yh);
    __nv_bfloat162 l = __halves2bfloat162(__float2bfloat16_rn(xr),
                                          __float2bfloat16_rn(yr));
    hi = *reinterpret_cast<uint32_t*>(&h);
    lo = *reinterpret_cast<uint32_t*>(&l);
}

__device__ __forceinline__ void mma_bf16(float* c, const uint32_t* a,
                                         const uint32_t* b) {
    asm volatile(
        "mma.sync.aligned.m16n8k16.row.col.f32.bf16.bf16.f32 "
        "{%0,%1,%2,%3}, {%4,%5,%6,%7}, {%8,%9}, {%0,%1,%2,%3};\n"
        : "+f"(c[0]), "+f"(c[1]), "+f"(c[2]), "+f"(c[3])
        : "r"(a[0]), "r"(a[1]), "r"(a[2]), "r"(a[3]), "r"(b[0]), "r"(b[1]));
}

__global__ __launch_bounds__(256) void mma_gemm_kernel(
    const float* __restrict__ A, const float* __restrict__ B,
    const float* __restrict__ bias, float* __restrict__ C,
    int M, int K, int N)
{
    // k-pair-packed bf16x2 words; row stride 17 words (16 pairs + pad)
    __shared__ uint32_t As_hi[128][17], As_lo[128][17];
    __shared__ uint32_t Bs_hi[64][17],  Bs_lo[64][17];

    int tid = threadIdx.x;
    int lane = tid & 31;
    int warp = tid >> 5;
    int warpM = warp >> 1;        // 0..3 -> 32 rows each
    int warpN = warp & 1;         // 0..1 -> 32 cols each
    int g = lane >> 2, tg = lane & 3;

    int m0 = blockIdx.y * 128;
    int n0 = blockIdx.x * 64;

    float acc[2][4][4];
    #pragma unroll
    for (int mt = 0; mt < 2; mt++)
        #pragma unroll
        for (int nt = 0; nt < 4; nt++)
            #pragma unroll
            for (int i = 0; i < 4; i++) acc[mt][nt][i] = 0.f;

    for (int k0 = 0; k0 < K; k0 += 32) {
        // load + split A tile: 128 rows x 32 cols = 1024 float4, 4/thread
        #pragma unroll
        for (int i = 0; i < 4; i++) {
            int f = tid + i * 256;
            int r = f >> 3;
            int q = f & 7;
            float4 v = make_float4(0.f, 0.f, 0.f, 0.f);
            int gm = m0 + r;
            if (gm < M) v = *(const float4*)(A + (size_t)gm * K + k0 + q * 4);
            uint32_t h0, l0, h1, l1;
            bf16_split2(v.x, v.y, h0, l0);
            bf16_split2(v.z, v.w, h1, l1);
            As_hi[r][q * 2] = h0;     As_lo[r][q * 2] = l0;
            As_hi[r][q * 2 + 1] = h1; As_lo[r][q * 2 + 1] = l1;
        }
        // load + split B tile: 32 rows x 64 cols, transposed to n-major k-pairs
        {
            int kp = tid >> 4;        // 0..15 (k pair index)
            int n4 = tid & 15;        // 0..15 (group of 4 n)
            const float* bp = B + (size_t)(k0 + kp * 2) * N + n0 + n4 * 4;
            float4 r0 = *(const float4*)bp;
            float4 r1 = *(const float4*)(bp + N);
            uint32_t h, l;
            bf16_split2(r0.x, r1.x, h, l); Bs_hi[n4*4+0][kp] = h; Bs_lo[n4*4+0][kp] = l;
            bf16_split2(r0.y, r1.y, h, l); Bs_hi[n4*4+1][kp] = h; Bs_lo[n4*4+1][kp] = l;
            bf16_split2(r0.z, r1.z, h, l); Bs_hi[n4*4+2][kp] = h; Bs_lo[n4*4+2][kp] = l;
            bf16_split2(r0.w, r1.w, h, l); Bs_hi[n4*4+3][kp] = h; Bs_lo[n4*4+3][kp] = l;
        }
        __syncthreads();

        #pragma unroll
        for (int ks = 0; ks < 2; ks++) {
            uint32_t ah[2][4], al[2][4], bh[4][2], bl[4][2];
            int kp = ks * 8 + tg;
            #pragma unroll
            for (int mt = 0; mt < 2; mt++) {
                int mr = warpM * 32 + mt * 16 + g;
                ah[mt][0] = As_hi[mr][kp];       al[mt][0] = As_lo[mr][kp];
                ah[mt][1] = As_hi[mr + 8][kp];   al[mt][1] = As_lo[mr + 8][kp];
                ah[mt][2] = As_hi[mr][kp + 4];   al[mt][2] = As_lo[mr][kp + 4];
                ah[mt][3] = As_hi[mr + 8][kp+4]; al[mt][3] = As_lo[mr + 8][kp+4];
            }
            #pragma unroll
            for (int nt = 0; nt < 4; nt++) {
                int nc = warpN * 32 + nt * 8 + g;
                bh[nt][0] = Bs_hi[nc][kp];       bl[nt][0] = Bs_lo[nc][kp];
                bh[nt][1] = Bs_hi[nc][kp + 4];   bl[nt][1] = Bs_lo[nc][kp + 4];
            }
            #pragma unroll
            for (int mt = 0; mt < 2; mt++)
                #pragma unroll
                for (int nt = 0; nt < 4; nt++) {
                    mma_bf16(acc[mt][nt], ah[mt], bh[nt]);
                    mma_bf16(acc[mt][nt], ah[mt], bl[nt]);
                    mma_bf16(acc[mt][nt], al[mt], bh[nt]);
                }
        }
        __syncthreads();
    }

    // epilogue
    #pragma unroll
    for (int nt = 0; nt < 4; nt++) {
        int col = n0 + warpN * 32 + nt * 8 + tg * 2;
        float2 bb = make_float2(0.f, 0.f);
        if (bias) { bb.x = bias[col]; bb.y = bias[col + 1]; }
        #pragma unroll
        for (int mt = 0; mt < 2; mt++) {
            int r0 = m0 + warpM * 32 + mt * 16 + g;
            if (r0 < M) {
                float2 v = make_float2(acc[mt][nt][0] + bb.x, acc[mt][nt][1] + bb.y);
                *(float2*)(C + (size_t)r0 * N + col) = v;
            }
            if (r0 + 8 < M) {
                float2 v = make_float2(acc[mt][nt][2] + bb.x, acc[mt][nt][3] + bb.y);
                *(float2*)(C + (size_t)(r0 + 8) * N + col) = v;
            }
        }
    }
}

// ---------------- per-node attention coefficients ---------------------------
__global__ __launch_bounds__(256) void alpha_kernel(
    const float* __restrict__ h,
    const float* __restrict__ asrc, const float* __restrict__ adst)
{
    int gw = (blockIdx.x * blockDim.x + threadIdx.x) >> 5;
    int lane = threadIdx.x & 31;
    if (gw >= N_NODES) return;
    const float4* h4 = (const float4*)(h + (size_t)gw * HID);
    const float4* s4 = (const float4*)asrc;
    const float4* d4 = (const float4*)adst;
    float4 v0 = h4[lane], v1 = h4[lane + 32];
    float4 a0 = s4[lane], a1 = s4[lane + 32];
    float4 b0 = d4[lane], b1 = d4[lane + 32];
    float ps = v0.x * a0.x + v0.y * a0.y + v0.z * a0.z + v0.w * a0.w
             + v1.x * a1.x + v1.y * a1.y + v1.z * a1.z + v1.w * a1.w;
    float pd = v0.x * b0.x + v0.y * b0.y + v0.z * b0.z + v0.w * b0.w
             + v1.x * b1.x + v1.y * b1.y + v1.z * b1.z + v1.w * b1.w;
    #pragma unroll
    for (int o = 16; o > 0; o >>= 1) {
        ps += __shfl_down_sync(0xFFFFFFFFu, ps, o);
        pd += __shfl_down_sync(0xFFFFFFFFu, pd, o);
    }
    if (lane == 0) { g_as[gw] = ps; g_ad[gw] = pd; }
}

// ---------------- softmax-weighted aggregation (warp per dst node) ----------
__global__ __launch_bounds__(256) void aggregate_kernel(
    const float* __restrict__ h, const float* __restrict__ bias,
    int do_relu, float* __restrict__ out)
{
    int n = (blockIdx.x * blockDim.x + threadIdx.x) >> 5;
    int lane = threadIdx.x & 31;
    if (n >= N_NODES) return;
    int start = g_off[n], end = g_off[n + 1];
    float ad = g_ad[n];
    float m = -3.4e38f, l = 0.f;
    float4 acc0 = make_float4(0.f, 0.f, 0.f, 0.f);
    float4 acc1 = make_float4(0.f, 0.f, 0.f, 0.f);

    for (int j = start; j < end; j++) {
        int s = g_srcidx[j];
        float e = g_as[s] + ad;
        e = e > 0.f ? e : 0.2f * e;           // LeakyReLU(0.2)
        if (e > m) {
            float sc = __expf(m - e);          // first iter: exp(-huge) = 0
            l *= sc;
            acc0.x *= sc; acc0.y *= sc; acc0.z *= sc; acc0.w *= sc;
            acc1.x *= sc; acc1.y *= sc; acc1.z *= sc; acc1.w *= sc;
            m = e;
        }
        float w = __expf(e - m);
        l += w;
        const float4* hr = (const float4*)(h + (size_t)s * HID);
        float4 v0 = hr[lane], v1 = hr[lane + 32];
        acc0.x += w * v0.x; acc0.y += w * v0.y; acc0.z += w * v0.z; acc0.w += w * v0.w;
        acc1.x += w * v1.x; acc1.y += w * v1.y; acc1.z += w * v1.z; acc1.w += w * v1.w;
    }
    float inv = 1.f / l;
    const float4* b4 = (const float4*)bias;
    float4 b0 = b4[lane], b1 = b4[lane + 32];
    float4 r0 = make_float4(acc0.x * inv + b0.x, acc0.y * inv + b0.y,
                            acc0.z * inv + b0.z, acc0.w * inv + b0.w);
    float4 r1 = make_float4(acc1.x * inv + b1.x, acc1.y * inv + b1.y,
                            acc1.z * inv + b1.z, acc1.w * inv + b1.w);
    if (do_relu) {
        r0.x = fmaxf(r0.x, 0.f); r0.y = fmaxf(r0.y, 0.f);
        r0.z = fmaxf(r0.z, 0.f); r0.w = fmaxf(r0.w, 0.f);
        r1.x = fmaxf(r1.x, 0.f); r1.y = fmaxf(r1.y, 0.f);
        r1.z = fmaxf(r1.z, 0.f); r1.w = fmaxf(r1.w, 0.f);
    }
    float4* o4 = (float4*)(out + (size_t)n * HID);
    o4[lane] = r0;
    o4[lane + 32] = r1;
}

// ---------------- edge output: out[e] = P[src[e]] + Q[dst[e]] ---------------
__global__ __launch_bounds__(256) void edge_out_kernel(
    const void* __restrict__ ei,
    const float* __restrict__ P, const float* __restrict__ Q,
    float* __restrict__ out)
{
    int gw = (blockIdx.x * blockDim.x + threadIdx.x) >> 5;
    int lane = threadIdx.x & 31;
    if (gw >= N_EDGES) return;
    int s = edge_at(ei, 0, gw);
    int d = edge_at(ei, 1, gw);
    const float4* P4 = (const float4*)(P + (size_t)s * HID);
    const float4* Q4 = (const float4*)(Q + (size_t)d * HID);
    float4* o4 = (float4*)(out + (size_t)gw * HID);
    float4 p0 = P4[lane], q0 = Q4[lane];
    float4 p1 = P4[lane + 32], q1 = Q4[lane + 32];
    o4[lane]      = make_float4(p0.x + q0.x, p0.y + q0.y, p0.z + q0.z, p0.w + q0.w);
    o4[lane + 32] = make_float4(p1.x + q1.x, p1.y + q1.y, p1.z + q1.z, p1.w + q1.w);
}

// ---------------- host launch ----------------------------------------------
extern "C" void kernel_launch(void* const* d_in, const int* in_sizes, int n_in,
                              void* d_out, int out_size)
{
    const float* x      = (const float*)d_in[0];
    const void*  ei     = d_in[1];
    const float* W1     = (const float*)d_in[2];
    const float* a1_src = (const float*)d_in[3];
    const float* a1_dst = (const float*)d_in[4];
    const float* b1     = (const float*)d_in[5];
    const float* W2     = (const float*)d_in[6];
    const float* a2_src = (const float*)d_in[7];
    const float* a2_dst = (const float*)d_in[8];
    const float* b2     = (const float*)d_in[9];
    const float* lin_W  = (const float*)d_in[10];
    const float* lin_b  = (const float*)d_in[11];
    float* out = (float*)d_out;

    float *h1, *h2, *P, *Q;
    cudaGetSymbolAddress((void**)&h1, g_h1);
    cudaGetSymbolAddress((void**)&h2, g_h2);
    cudaGetSymbolAddress((void**)&P,  g_P);
    cudaGetSymbolAddress((void**)&Q,  g_Q);

    const int TB = 256;
    int ebk = (N_EDGES + TB - 1) / TB;
    int nbk = (N_NODES + TB - 1) / TB;
    int wbk_n = (N_NODES * 32 + TB - 1) / TB;    // warp per node
    int wbk_e = (N_EDGES * 32 + TB - 1) / TB;    // warp per edge

    // dtype detect + CSR build (graph identical both layers)
    detect_kernel<<<1, 32>>>((const unsigned int*)ei);
    init_deg_kernel<<<nbk, TB>>>();
    count_kernel<<<ebk, TB>>>(ei);
    blocksum_kernel<<<SCAN_NB, SCAN_B>>>();
    scan_blocks_kernel<<<1, 32>>>();
    write_off_kernel<<<SCAN_NB, SCAN_B>>>();
    fill_kernel<<<ebk, TB>>>(ei);

    dim3 gemm_grid(HID / 64, (N_NODES + 127) / 128);  // (4, 391)

    // layer 1: h1 = x @ W1 ; softmax-aggregate (+b1, relu) -> h2
    mma_gemm_kernel<<<gemm_grid, TB>>>(x, W1, nullptr, h1, N_NODES, 128, HID);
    alpha_kernel<<<wbk_n, TB>>>(h1, a1_src, a1_dst);
    aggregate_kernel<<<wbk_n, TB>>>(h1, b1, 1, h2);

    // layer 2: h1 = h2 @ W2 ; aggregate (+b2) -> h2
    mma_gemm_kernel<<<gemm_grid, TB>>>(h2, W2, nullptr, h1, N_NODES, HID, HID);
    alpha_kernel<<<wbk_n, TB>>>(h1, a2_src, a2_dst);
    aggregate_kernel<<<wbk_n, TB>>>(h1, b2, 0, h2);

    // final: P = h2 @ lin_W[:256] + lin_b ; Q = h2 @ lin_W[256:]
    mma_gemm_kernel<<<gemm_grid, TB>>>(h2, lin_W, lin_b, P, N_NODES, HID, HID);
    mma_gemm_kernel<<<gemm_grid, TB>>>(h2, lin_W + (size_t)HID * HID, nullptr, Q,
                                       N_NODES, HID, HID);

    // out[e] = P[src] + Q[dst]
    edge_out_kernel<<<wbk_e, TB>>>(ei, P, Q, out);
}